// round 11
// baseline (speedup 1.0000x reference)
#include <cuda_runtime.h>
#include <cuda_fp16.h>

// Problem constants (fixed by the dataset)
#define N_BATCH 2
#define HW 65536          // 256*256
#define NRAYS 32768       // N_BATCH * 16384
#define RPW 2             // rays per warp
#define RPB 8             // rays per block (4 warps x 2)
#define THREADS 128

typedef unsigned long long u64;
typedef unsigned int u32;

// channels-last fp16 copy of the planes: [(n*3+p)][hw][c]
__device__ __half g_planesH[(size_t)N_BATCH * 3 * HW * 32];

// ---- dynamic smem layout (bytes) ----
#define SM_W1H    0        // 2048 half [c][j]
#define SM_W2H    4096     // 2048 half [j][32 rgb outputs]
#define SM_B1S    8192     // 64 f32
#define SM_W2SIG  8448     // 64 f32
#define SM_B2RS   8704     // 32 f32
#define SM_B2SIG  8832     // 1 f32 (+pad)
#define SM_TAPS   8960     // 4 warps x 32 x 12 int2 = 12288
#define SM_FEATS  21248    // 4 warps x 2 rays x (32*33) f32 = 33792
#define SM_TOTAL  55040

// ---------- packed f32x2 helpers ----------
__device__ __forceinline__ u64 ffma2(u64 a, u64 b, u64 c) {
    u64 r; asm("fma.rn.f32x2 %0,%1,%2,%3;" : "=l"(r) : "l"(a), "l"(b), "l"(c)); return r;
}
__device__ __forceinline__ u64 pack2(float lo, float hi) {
    u64 r; asm("mov.b64 %0,{%1,%2};" : "=l"(r) : "f"(lo), "f"(hi)); return r;
}
__device__ __forceinline__ void unpack2(u64 d, float& lo, float& hi) {
    asm("mov.b64 {%0,%1},%2;" : "=f"(lo), "=f"(hi) : "l"(d));
}
// half2 bits -> packed f32x2
__device__ __forceinline__ u64 h2u(u32 h2bits) {
    __half2 hv = *reinterpret_cast<__half2*>(&h2bits);
    float2 f = __half22float2(hv);
    return pack2(f.x, f.y);
}
__device__ __forceinline__ float softplus_f(float x) {
    return fmaxf(x, 0.f) + __logf(1.f + __expf(-fabsf(x)));
}

// ---------- kernel 0: [np][C][HW] f32 -> [np][HW][C] fp16 transpose ----------
__global__ void transpose_kernel(const float* __restrict__ in) {
    __shared__ float tile[32][33];
    int np  = blockIdx.y;
    int hw0 = blockIdx.x * 32;
    int tx = threadIdx.x, ty = threadIdx.y;
#pragma unroll
    for (int i = 0; i < 4; i++) {
        int cc = ty * 4 + i;
        tile[cc][tx] = in[(np * 32 + cc) * HW + hw0 + tx];
    }
    __syncthreads();
#pragma unroll
    for (int i = 0; i < 4; i++) {
        int row = ty * 4 + i;
        g_planesH[(size_t)(np * HW + hw0 + row) * 32 + tx] = __float2half(tile[tx][row]);
    }
}

// ---------- kernel 1: renderer, one warp per 2 rays ----------
__global__ __launch_bounds__(THREADS, 3) void render_kernel(
    const float* __restrict__ orig, const float* __restrict__ dirs,
    const float* __restrict__ w1, const float* __restrict__ b1,
    const float* __restrict__ w2, const float* __restrict__ b2,
    float* __restrict__ out)
{
    extern __shared__ __align__(16) unsigned char smem[];
    __half* w1h   = (__half*)(smem + SM_W1H);
    __half* w2h   = (__half*)(smem + SM_W2H);
    float* b1s    = (float*)(smem + SM_B1S);
    float* w2sigs = (float*)(smem + SM_W2SIG);
    float* b2rs   = (float*)(smem + SM_B2RS);
    float* b2sigp = (float*)(smem + SM_B2SIG);
    int2*  taps   = (int2*)(smem + SM_TAPS);
    float* featsb = (float*)(smem + SM_FEATS);

    const int tid = threadIdx.x;
    for (int i = tid; i < 2048; i += THREADS) w1h[i] = __float2half(w1[i]);
    if (tid < 64) b1s[tid] = b1[tid];
    for (int i = tid; i < 64 * 33; i += THREADS) {
        int j = i / 33, k = i - j * 33;
        float v = w2[i];
        if (k == 0) w2sigs[j] = v; else w2h[j * 32 + (k - 1)] = __float2half(v);
    }
    if (tid < 32) b2rs[tid] = b2[tid + 1];
    if (tid == 0) b2sigp[0] = b2[0];
    __syncthreads();

    const int w = tid >> 5, lane = tid & 31;
    const int rg0 = blockIdx.x * RPB + w * RPW;   // first ray of this warp
    const unsigned FULL = 0xffffffffu;

    const float t   = (lane + 0.5f) * 0.03125f;
    const float dep = 2.25f + 1.05f * t;

    // ---- stage 1+2 per ray: taps (lane = sample), then shuffle-free gather ----
#pragma unroll
    for (int r = 0; r < RPW; r++) {
        const int rg = rg0 + r;
        const int n  = rg >> 14;
        const float ox = orig[rg * 3 + 0], oy = orig[rg * 3 + 1], oz = orig[rg * 3 + 2];
        const float dx = dirs[rg * 3 + 0], dy = dirs[rg * 3 + 1], dz = dirs[rg * 3 + 2];
        const float cx = 2.f * fmaf(dep, dx, ox);
        const float cy = 2.f * fmaf(dep, dy, oy);
        const float cz = 2.f * fmaf(dep, dz, oz);

#pragma unroll
        for (int p = 0; p < 3; p++) {
            float u = (p == 0) ? cx : (p == 1) ? cy : cx;
            float v = (p == 0) ? cy : (p == 1) ? cz : cz;
            float ix = ((u + 1.f) * 0.5f) * 255.f;
            float iy = ((v + 1.f) * 0.5f) * 255.f;
            float fx0 = floorf(ix), fy0 = floorf(iy);
            float a0 = ix - fx0, a1 = (fx0 + 1.f) - ix;
            float bb0 = iy - fy0, bb1 = (fy0 + 1.f) - iy;
            int ix0 = (int)fminf(fmaxf(fx0, 0.f), 255.f);
            int ix1 = (int)fminf(fmaxf(fx0 + 1.f, 0.f), 255.f);
            int iy0 = (int)fminf(fmaxf(fy0, 0.f), 255.f);
            int iy1 = (int)fminf(fmaxf(fy0 + 1.f, 0.f), 255.f);
            int base = (n * 3 + p) * (HW * 32);
            int r0 = base + iy0 * (256 * 32);
            int r1 = base + iy1 * (256 * 32);
            int o = (w * 32 + lane) * 12 + p * 4;
            taps[o + 0] = make_int2(r0 + ix0 * 32, __float_as_int(a1 * bb1));
            taps[o + 1] = make_int2(r0 + ix1 * 32, __float_as_int(a0 * bb1));
            taps[o + 2] = make_int2(r1 + ix0 * 32, __float_as_int(a1 * bb0));
            taps[o + 3] = make_int2(r1 + ix1 * 32, __float_as_int(a0 * bb0));
        }
        __syncwarp();

        // gather: lanes = 8 channel-quads x 4 samples; each lane privately
        // accumulates all 12 taps of its sample for its 4 channels (fp16 loads).
        {
            const int q    = lane & 7;           // channel quad
            const int sub  = lane >> 3;          // sample sub-index
            const int cpos = q * 4;
            float* feats = featsb + (w * 2 + r) * (32 * 33);
#pragma unroll 2
            for (int sb = 0; sb < 32; sb += 4) {
                const int s = sb + sub;
                float a0 = 0.f, a1 = 0.f, a2 = 0.f, a3 = 0.f;
#pragma unroll
                for (int tp = 0; tp < 12; tp++) {
                    int2 tw = taps[(w * 32 + s) * 12 + tp];
                    float wt = __int_as_float(tw.y);
                    uint2 raw = *(const uint2*)&g_planesH[tw.x + cpos];
                    float2 f01 = __half22float2(*reinterpret_cast<__half2*>(&raw.x));
                    float2 f23 = __half22float2(*reinterpret_cast<__half2*>(&raw.y));
                    a0 = fmaf(wt, f01.x, a0);
                    a1 = fmaf(wt, f01.y, a1);
                    a2 = fmaf(wt, f23.x, a2);
                    a3 = fmaf(wt, f23.y, a3);
                }
                float* f = feats + s * 33 + cpos;
                f[0] = a0 * (1.f / 3.f);
                f[1] = a1 * (1.f / 3.f);
                f[2] = a2 * (1.f / 3.f);
                f[3] = a3 * (1.f / 3.f);
            }
        }
        __syncwarp();
    }

    // ---- MLP for both samples (lane's sample of ray0 and ray1) ----
    const float* frow0 = featsb + (w * 2 + 0) * (32 * 33) + lane * 33;
    const float* frow1 = featsb + (w * 2 + 1) * (32 * 33) + lane * 33;

    const float b2sig = b2sigp[0];
    float sig0 = b2sig, sig1 = b2sig;
    u64 a20[16], a21[16];
    const u64* b2d = (const u64*)b2rs;
#pragma unroll
    for (int k = 0; k < 16; k++) { a20[k] = b2d[k]; a21[k] = b2d[k]; }

    const u64* b1d = (const u64*)b1s;

#pragma unroll
    for (int q = 0; q < 4; q++) {       // 16 hidden units per quarter
        u64 ac0[8], ac1[8];
#pragma unroll
        for (int jp = 0; jp < 8; jp++) { ac0[jp] = b1d[q * 8 + jp]; ac1[jp] = ac0[jp]; }

#pragma unroll 4
        for (int cc = 0; cc < 32; cc++) {
            float f0 = frow0[cc], f1 = frow1[cc];
            u64 f02 = pack2(f0, f0), f12 = pack2(f1, f1);
            const uint4* wr = (const uint4*)(w1h + cc * 64 + q * 16);  // 16 halves
#pragma unroll
            for (int hh = 0; hh < 2; hh++) {
                uint4 hw = wr[hh];
                u64 w0 = h2u(hw.x), w1v = h2u(hw.y), w2v = h2u(hw.z), w3v = h2u(hw.w);
                ac0[hh * 4 + 0] = ffma2(f02, w0,  ac0[hh * 4 + 0]);
                ac0[hh * 4 + 1] = ffma2(f02, w1v, ac0[hh * 4 + 1]);
                ac0[hh * 4 + 2] = ffma2(f02, w2v, ac0[hh * 4 + 2]);
                ac0[hh * 4 + 3] = ffma2(f02, w3v, ac0[hh * 4 + 3]);
                ac1[hh * 4 + 0] = ffma2(f12, w0,  ac1[hh * 4 + 0]);
                ac1[hh * 4 + 1] = ffma2(f12, w1v, ac1[hh * 4 + 1]);
                ac1[hh * 4 + 2] = ffma2(f12, w2v, ac1[hh * 4 + 2]);
                ac1[hh * 4 + 3] = ffma2(f12, w3v, ac1[hh * 4 + 3]);
            }
        }
        // consume the 16 hidden units of this quarter into layer 2
#pragma unroll 4
        for (int jp = 0; jp < 8; jp++) {
            int j0 = q * 16 + 2 * jp;
            float l0, h0, l1, h1;
            unpack2(ac0[jp], l0, h0);
            unpack2(ac1[jp], l1, h1);
            float h00 = softplus_f(l0), h01 = softplus_f(h0);
            float h10 = softplus_f(l1), h11 = softplus_f(h1);
            float ws0 = w2sigs[j0], ws1 = w2sigs[j0 + 1];
            sig0 = fmaf(h00, ws0, sig0); sig0 = fmaf(h01, ws1, sig0);
            sig1 = fmaf(h10, ws0, sig1); sig1 = fmaf(h11, ws1, sig1);
            u64 p00 = pack2(h00, h00), p01 = pack2(h01, h01);
            u64 p10 = pack2(h10, h10), p11 = pack2(h11, h11);
            const uint4* wr0 = (const uint4*)(w2h + j0 * 32);        // 32 halves
            const uint4* wr1 = (const uint4*)(w2h + (j0 + 1) * 32);
#pragma unroll
            for (int kq = 0; kq < 4; kq++) {
                uint4 q0 = wr0[kq];
                uint4 q1 = wr1[kq];
                u64 w00 = h2u(q0.x), w01 = h2u(q0.y), w02 = h2u(q0.z), w03 = h2u(q0.w);
                u64 w10 = h2u(q1.x), w11 = h2u(q1.y), w12 = h2u(q1.z), w13 = h2u(q1.w);
                a20[kq * 4 + 0] = ffma2(p01, w10, ffma2(p00, w00, a20[kq * 4 + 0]));
                a20[kq * 4 + 1] = ffma2(p01, w11, ffma2(p00, w01, a20[kq * 4 + 1]));
                a20[kq * 4 + 2] = ffma2(p01, w12, ffma2(p00, w02, a20[kq * 4 + 2]));
                a20[kq * 4 + 3] = ffma2(p01, w13, ffma2(p00, w03, a20[kq * 4 + 3]));
                a21[kq * 4 + 0] = ffma2(p11, w10, ffma2(p10, w00, a21[kq * 4 + 0]));
                a21[kq * 4 + 1] = ffma2(p11, w11, ffma2(p10, w01, a21[kq * 4 + 1]));
                a21[kq * 4 + 2] = ffma2(p11, w12, ffma2(p10, w02, a21[kq * 4 + 2]));
                a21[kq * 4 + 3] = ffma2(p11, w13, ffma2(p10, w03, a21[kq * 4 + 3]));
            }
        }
    }

    // ---- ray marching per ray: warp scan over samples (lane = s) ----
#pragma unroll
    for (int r = 0; r < RPW; r++) {
        float sig = (r == 0) ? sig0 : sig1;
        float rgb[32];
#pragma unroll
        for (int k = 0; k < 16; k++) {
            u64 av = (r == 0) ? a20[k] : a21[k];
            float lo, hi; unpack2(av, lo, hi);
            rgb[2 * k]     = __fdividef(1.002f, 1.f + __expf(-lo)) - 0.001f;
            rgb[2 * k + 1] = __fdividef(1.002f, 1.f + __expf(-hi)) - 0.001f;
        }

        float sig_n = __shfl_down_sync(FULL, sig, 1);
        float dep_n = __shfl_down_sync(FULL, dep, 1);
        float alpha;
        if (lane < 31) {
            float delta = dep_n - dep;
            float dm = 0.5f * (sig + sig_n);
            float dens = softplus_f(dm - 1.f);
            alpha = 1.f - __expf(-delta * dens);
        } else {
            alpha = 0.f;
        }
        float gg = 1.f - alpha + 1e-10f;
        float pscan = gg;
#pragma unroll
        for (int off = 1; off < 32; off <<= 1) {
            float v = __shfl_up_sync(FULL, pscan, off);
            if (lane >= off) pscan *= v;
        }
        float T = __shfl_up_sync(FULL, pscan, 1);
        if (lane == 0) T = 1.f;
        float wgt = alpha * T;
        float wprev = __shfl_up_sync(FULL, wgt, 1);
        if (lane == 0) wprev = 0.f;
        float coeff = 0.5f * (wgt + wprev);

#pragma unroll
        for (int k = 0; k < 32; k++) rgb[k] *= coeff;
#pragma unroll
        for (int off = 16; off >= 1; off >>= 1) {
#pragma unroll
            for (int k = 0; k < 32; k++) rgb[k] += __shfl_xor_sync(FULL, rgb[k], off);
        }
        if (lane == 0) {
            float4* o4 = (float4*)(out + (rg0 + r) * 32);
#pragma unroll
            for (int k = 0; k < 8; k++)
                o4[k] = make_float4(rgb[4 * k], rgb[4 * k + 1], rgb[4 * k + 2], rgb[4 * k + 3]);
        }
    }
}

extern "C" void kernel_launch(void* const* d_in, const int* in_sizes, int n_in,
                              void* d_out, int out_size) {
    const float* vol  = (const float*)d_in[0];  // [2,3,32,256,256]
    const float* orig = (const float*)d_in[1];  // [2,16384,3]
    const float* dirs = (const float*)d_in[2];  // [2,16384,3]
    const float* w1   = (const float*)d_in[3];  // [32,64]
    const float* b1   = (const float*)d_in[4];  // [64]
    const float* w2   = (const float*)d_in[5];  // [64,33]
    const float* b2   = (const float*)d_in[6];  // [33]
    float* out = (float*)d_out;

    static int inited = 0;
    if (!inited) {
        cudaFuncSetAttribute(render_kernel,
                             cudaFuncAttributeMaxDynamicSharedMemorySize, SM_TOTAL);
        inited = 1;
    }

    dim3 tb(32, 8);
    dim3 tg(HW / 32, N_BATCH * 3);
    transpose_kernel<<<tg, tb>>>(vol);

    render_kernel<<<NRAYS / RPB, THREADS, SM_TOTAL>>>(orig, dirs, w1, b1, w2, b2, out);
}

// round 12
// speedup vs baseline: 2.0618x; 2.0618x over previous
#include <cuda_runtime.h>
#include <cuda_fp16.h>

// Problem constants (fixed by the dataset)
#define N_BATCH 2
#define HW 65536          // 256*256
#define NRAYS 32768       // N_BATCH * 16384
#define RPW 2             // rays per warp
#define RPB 8             // rays per block (4 warps x 2)
#define THREADS 128
#define FPITCH 17         // feats row pitch in u32 (34 halves)

typedef unsigned long long u64;
typedef unsigned int u32;

// channels-last fp16 copy of the planes: [(n*3+p)][hw][c]
__device__ __half g_planesH[(size_t)N_BATCH * 3 * HW * 32];

// ---- dynamic smem layout (bytes) ----
#define SM_W1S    0        // 2048 f32  [c][j]
#define SM_W2RS   8192     // 2048 f32  [j][32 rgb outputs]
#define SM_B1S    16384    // 64 f32
#define SM_W2SIG  16640    // 64 f32
#define SM_B2RS   16896    // 32 f32
#define SM_B2SIG  17024    // 1 f32 (+pad)
#define SM_TAPS   17152    // 4 warps x 32 x 12 int2 = 12288
#define SM_FEATS  29440    // 4 warps x 2 rays x 32*34 halves = 17408
#define SM_TOTAL  46848

// ---------- packed f32x2 helpers ----------
__device__ __forceinline__ u64 ffma2(u64 a, u64 b, u64 c) {
    u64 r; asm("fma.rn.f32x2 %0,%1,%2,%3;" : "=l"(r) : "l"(a), "l"(b), "l"(c)); return r;
}
__device__ __forceinline__ u64 pack2(float lo, float hi) {
    u64 r; asm("mov.b64 %0,{%1,%2};" : "=l"(r) : "f"(lo), "f"(hi)); return r;
}
__device__ __forceinline__ void unpack2(u64 d, float& lo, float& hi) {
    asm("mov.b64 {%0,%1},%2;" : "=f"(lo), "=f"(hi) : "l"(d));
}
__device__ __forceinline__ float softplus_f(float x) {
    return fmaxf(x, 0.f) + __logf(1.f + __expf(-fabsf(x)));
}

// ---------- kernel 0: [np][C][HW] f32 -> [np][HW][C] fp16 transpose ----------
__global__ void transpose_kernel(const float* __restrict__ in) {
    __shared__ float tile[32][33];
    int np  = blockIdx.y;
    int hw0 = blockIdx.x * 32;
    int tx = threadIdx.x, ty = threadIdx.y;
#pragma unroll
    for (int i = 0; i < 4; i++) {
        int cc = ty * 4 + i;
        tile[cc][tx] = in[(np * 32 + cc) * HW + hw0 + tx];
    }
    __syncthreads();
#pragma unroll
    for (int i = 0; i < 4; i++) {
        int row = ty * 4 + i;
        g_planesH[(size_t)(np * HW + hw0 + row) * 32 + tx] = __float2half(tile[tx][row]);
    }
}

// ---------- kernel 1: renderer, one warp per 2 rays, 4 blocks/SM ----------
__global__ __launch_bounds__(THREADS, 4) void render_kernel(
    const float* __restrict__ orig, const float* __restrict__ dirs,
    const float* __restrict__ w1, const float* __restrict__ b1,
    const float* __restrict__ w2, const float* __restrict__ b2,
    float* __restrict__ out)
{
    extern __shared__ __align__(16) unsigned char smem[];
    float* w1s    = (float*)(smem + SM_W1S);
    float* w2rs   = (float*)(smem + SM_W2RS);
    float* b1s    = (float*)(smem + SM_B1S);
    float* w2sigs = (float*)(smem + SM_W2SIG);
    float* b2rs   = (float*)(smem + SM_B2RS);
    float* b2sigp = (float*)(smem + SM_B2SIG);
    int2*  taps   = (int2*)(smem + SM_TAPS);
    u32*   featsb = (u32*)(smem + SM_FEATS);   // half2 lattice, pitch FPITCH u32

    const int tid = threadIdx.x;
    for (int i = tid; i < 2048; i += THREADS) w1s[i] = w1[i];
    if (tid < 64) b1s[tid] = b1[tid];
    for (int i = tid; i < 64 * 33; i += THREADS) {
        int j = i / 33, k = i - j * 33;
        float v = w2[i];
        if (k == 0) w2sigs[j] = v; else w2rs[j * 32 + (k - 1)] = v;
    }
    if (tid < 32) b2rs[tid] = b2[tid + 1];
    if (tid == 0) b2sigp[0] = b2[0];
    __syncthreads();

    const int w = tid >> 5, lane = tid & 31;
    const int rg0 = blockIdx.x * RPB + w * RPW;   // first ray of this warp
    const unsigned FULL = 0xffffffffu;

    const float t   = (lane + 0.5f) * 0.03125f;
    const float dep = 2.25f + 1.05f * t;

    // ---- stage 1+2 per ray: taps (lane = sample), then shuffle-free gather ----
#pragma unroll
    for (int r = 0; r < RPW; r++) {
        const int rg = rg0 + r;
        const int n  = rg >> 14;
        const float ox = orig[rg * 3 + 0], oy = orig[rg * 3 + 1], oz = orig[rg * 3 + 2];
        const float dx = dirs[rg * 3 + 0], dy = dirs[rg * 3 + 1], dz = dirs[rg * 3 + 2];
        const float cx = 2.f * fmaf(dep, dx, ox);
        const float cy = 2.f * fmaf(dep, dy, oy);
        const float cz = 2.f * fmaf(dep, dz, oz);

#pragma unroll
        for (int p = 0; p < 3; p++) {
            float u = (p == 0) ? cx : (p == 1) ? cy : cx;
            float v = (p == 0) ? cy : (p == 1) ? cz : cz;
            float ix = ((u + 1.f) * 0.5f) * 255.f;
            float iy = ((v + 1.f) * 0.5f) * 255.f;
            float fx0 = floorf(ix), fy0 = floorf(iy);
            float a0 = ix - fx0, a1 = (fx0 + 1.f) - ix;
            float bb0 = iy - fy0, bb1 = (fy0 + 1.f) - iy;
            int ix0 = (int)fminf(fmaxf(fx0, 0.f), 255.f);
            int ix1 = (int)fminf(fmaxf(fx0 + 1.f, 0.f), 255.f);
            int iy0 = (int)fminf(fmaxf(fy0, 0.f), 255.f);
            int iy1 = (int)fminf(fmaxf(fy0 + 1.f, 0.f), 255.f);
            int base = (n * 3 + p) * (HW * 32);
            int r0 = base + iy0 * (256 * 32);
            int r1 = base + iy1 * (256 * 32);
            int o = (w * 32 + lane) * 12 + p * 4;
            taps[o + 0] = make_int2(r0 + ix0 * 32, __float_as_int(a1 * bb1));
            taps[o + 1] = make_int2(r0 + ix1 * 32, __float_as_int(a0 * bb1));
            taps[o + 2] = make_int2(r1 + ix0 * 32, __float_as_int(a1 * bb0));
            taps[o + 3] = make_int2(r1 + ix1 * 32, __float_as_int(a0 * bb0));
        }
        __syncwarp();

        // gather: lanes = 8 channel-quads x 4 samples; each lane privately
        // accumulates all 12 taps of its sample for its 4 channels (fp16 loads).
        {
            const int q    = lane & 7;           // channel quad
            const int sub  = lane >> 3;          // sample sub-index
            const int cpos = q * 4;
            u32* feats = featsb + (w * 2 + r) * (32 * FPITCH);
#pragma unroll 2
            for (int sb = 0; sb < 32; sb += 4) {
                const int s = sb + sub;
                float a0 = 0.f, a1 = 0.f, a2 = 0.f, a3 = 0.f;
#pragma unroll
                for (int tp = 0; tp < 12; tp++) {
                    int2 tw = taps[(w * 32 + s) * 12 + tp];
                    float wt = __int_as_float(tw.y);
                    uint2 raw = *(const uint2*)&g_planesH[tw.x + cpos];
                    float2 f01 = __half22float2(*reinterpret_cast<__half2*>(&raw.x));
                    float2 f23 = __half22float2(*reinterpret_cast<__half2*>(&raw.y));
                    a0 = fmaf(wt, f01.x, a0);
                    a1 = fmaf(wt, f01.y, a1);
                    a2 = fmaf(wt, f23.x, a2);
                    a3 = fmaf(wt, f23.y, a3);
                }
                __half2 p0 = __floats2half2_rn(a0 * (1.f / 3.f), a1 * (1.f / 3.f));
                __half2 p1 = __floats2half2_rn(a2 * (1.f / 3.f), a3 * (1.f / 3.f));
                feats[s * FPITCH + q * 2]     = *reinterpret_cast<u32*>(&p0);
                feats[s * FPITCH + q * 2 + 1] = *reinterpret_cast<u32*>(&p1);
            }
        }
        __syncwarp();
    }

    // ---- MLP for both samples (lane's sample of ray0 and ray1) ----
    const u32* frow0 = featsb + (w * 2 + 0) * (32 * FPITCH) + lane * FPITCH;
    const u32* frow1 = featsb + (w * 2 + 1) * (32 * FPITCH) + lane * FPITCH;

    const float b2sig = b2sigp[0];
    float sig0 = b2sig, sig1 = b2sig;
    u64 a20[16], a21[16];
    const u64* b2d = (const u64*)b2rs;
#pragma unroll
    for (int k = 0; k < 16; k++) { a20[k] = b2d[k]; a21[k] = b2d[k]; }

    const ulonglong2* w1d2 = (const ulonglong2*)w1s;
    const ulonglong2* w2d2 = (const ulonglong2*)w2rs;
    const u64* b1d = (const u64*)b1s;

#pragma unroll
    for (int q = 0; q < 4; q++) {       // 16 hidden units per quarter
        u64 ac0[8], ac1[8];
#pragma unroll
        for (int jp = 0; jp < 8; jp++) { ac0[jp] = b1d[q * 8 + jp]; ac1[jp] = ac0[jp]; }

#pragma unroll 4
        for (int c2 = 0; c2 < 16; c2++) {      // channel pairs
            u32 r0b = frow0[c2], r1b = frow1[c2];
            float2 f0 = __half22float2(*reinterpret_cast<__half2*>(&r0b));
            float2 f1 = __half22float2(*reinterpret_cast<__half2*>(&r1b));
#pragma unroll
            for (int e = 0; e < 2; e++) {
                float fe0 = (e == 0) ? f0.x : f0.y;
                float fe1 = (e == 0) ? f1.x : f1.y;
                u64 f02 = pack2(fe0, fe0), f12 = pack2(fe1, fe1);
                const ulonglong2* wr = w1d2 + (2 * c2 + e) * 16 + q * 4;
#pragma unroll
                for (int jq = 0; jq < 4; jq++) {
                    ulonglong2 ww = wr[jq];
                    ac0[2 * jq]     = ffma2(f02, ww.x, ac0[2 * jq]);
                    ac0[2 * jq + 1] = ffma2(f02, ww.y, ac0[2 * jq + 1]);
                    ac1[2 * jq]     = ffma2(f12, ww.x, ac1[2 * jq]);
                    ac1[2 * jq + 1] = ffma2(f12, ww.y, ac1[2 * jq + 1]);
                }
            }
        }
        // consume the 16 hidden units of this quarter into layer 2
#pragma unroll 4
        for (int jp = 0; jp < 8; jp++) {
            int j0 = q * 16 + 2 * jp;
            float l0, h0, l1, h1;
            unpack2(ac0[jp], l0, h0);
            unpack2(ac1[jp], l1, h1);
            float h00 = softplus_f(l0), h01 = softplus_f(h0);
            float h10 = softplus_f(l1), h11 = softplus_f(h1);
            float ws0 = w2sigs[j0], ws1 = w2sigs[j0 + 1];
            sig0 = fmaf(h00, ws0, sig0); sig0 = fmaf(h01, ws1, sig0);
            sig1 = fmaf(h10, ws0, sig1); sig1 = fmaf(h11, ws1, sig1);
            u64 p00 = pack2(h00, h00), p01 = pack2(h01, h01);
            u64 p10 = pack2(h10, h10), p11 = pack2(h11, h11);
            const ulonglong2* wr0 = w2d2 + j0 * 8;
#pragma unroll
            for (int kq = 0; kq < 8; kq++) {
                ulonglong2 ww0 = wr0[kq];
                ulonglong2 ww1 = wr0[8 + kq];
                u64 v0 = ffma2(p00, ww0.x, a20[2 * kq]);
                u64 v1 = ffma2(p00, ww0.y, a20[2 * kq + 1]);
                a20[2 * kq]     = ffma2(p01, ww1.x, v0);
                a20[2 * kq + 1] = ffma2(p01, ww1.y, v1);
                u64 u0 = ffma2(p10, ww0.x, a21[2 * kq]);
                u64 u1 = ffma2(p10, ww0.y, a21[2 * kq + 1]);
                a21[2 * kq]     = ffma2(p11, ww1.x, u0);
                a21[2 * kq + 1] = ffma2(p11, ww1.y, u1);
            }
        }
    }

    // ---- ray marching per ray: warp scan over samples (lane = s) ----
#pragma unroll
    for (int r = 0; r < RPW; r++) {
        float sig = (r == 0) ? sig0 : sig1;
        float rgb[32];
#pragma unroll
        for (int k = 0; k < 16; k++) {
            u64 av = (r == 0) ? a20[k] : a21[k];
            float lo, hi; unpack2(av, lo, hi);
            rgb[2 * k]     = __fdividef(1.002f, 1.f + __expf(-lo)) - 0.001f;
            rgb[2 * k + 1] = __fdividef(1.002f, 1.f + __expf(-hi)) - 0.001f;
        }

        float sig_n = __shfl_down_sync(FULL, sig, 1);
        float dep_n = __shfl_down_sync(FULL, dep, 1);
        float alpha;
        if (lane < 31) {
            float delta = dep_n - dep;
            float dm = 0.5f * (sig + sig_n);
            float dens = softplus_f(dm - 1.f);
            alpha = 1.f - __expf(-delta * dens);
        } else {
            alpha = 0.f;
        }
        float gg = 1.f - alpha + 1e-10f;
        float pscan = gg;
#pragma unroll
        for (int off = 1; off < 32; off <<= 1) {
            float v = __shfl_up_sync(FULL, pscan, off);
            if (lane >= off) pscan *= v;
        }
        float T = __shfl_up_sync(FULL, pscan, 1);
        if (lane == 0) T = 1.f;
        float wgt = alpha * T;
        float wprev = __shfl_up_sync(FULL, wgt, 1);
        if (lane == 0) wprev = 0.f;
        float coeff = 0.5f * (wgt + wprev);

#pragma unroll
        for (int k = 0; k < 32; k++) rgb[k] *= coeff;
#pragma unroll
        for (int off = 16; off >= 1; off >>= 1) {
#pragma unroll
            for (int k = 0; k < 32; k++) rgb[k] += __shfl_xor_sync(FULL, rgb[k], off);
        }
        if (lane == 0) {
            float4* o4 = (float4*)(out + (rg0 + r) * 32);
#pragma unroll
            for (int k = 0; k < 8; k++)
                o4[k] = make_float4(rgb[4 * k], rgb[4 * k + 1], rgb[4 * k + 2], rgb[4 * k + 3]);
        }
    }
}

extern "C" void kernel_launch(void* const* d_in, const int* in_sizes, int n_in,
                              void* d_out, int out_size) {
    const float* vol  = (const float*)d_in[0];  // [2,3,32,256,256]
    const float* orig = (const float*)d_in[1];  // [2,16384,3]
    const float* dirs = (const float*)d_in[2];  // [2,16384,3]
    const float* w1   = (const float*)d_in[3];  // [32,64]
    const float* b1   = (const float*)d_in[4];  // [64]
    const float* w2   = (const float*)d_in[5];  // [64,33]
    const float* b2   = (const float*)d_in[6];  // [33]
    float* out = (float*)d_out;

    static int inited = 0;
    if (!inited) {
        cudaFuncSetAttribute(render_kernel,
                             cudaFuncAttributeMaxDynamicSharedMemorySize, SM_TOTAL);
        inited = 1;
    }

    dim3 tb(32, 8);
    dim3 tg(HW / 32, N_BATCH * 3);
    transpose_kernel<<<tg, tb>>>(vol);

    render_kernel<<<NRAYS / RPB, THREADS, SM_TOTAL>>>(orig, dirs, w1, b1, w2, b2, out);
}

// round 13
// speedup vs baseline: 2.1357x; 1.0358x over previous
#include <cuda_runtime.h>
#include <cuda_fp16.h>

// Problem constants (fixed by the dataset)
#define N_BATCH 2
#define HW 65536          // 256*256
#define NRAYS 32768       // N_BATCH * 16384
#define RPW 2             // rays per warp
#define RPB 8             // rays per block (4 warps x 2)
#define THREADS 128
#define FPITCH 17         // feats row pitch in u32 (34 halves)

typedef unsigned long long u64;
typedef unsigned int u32;

// channels-last fp16 copy of the planes: [(n*3+p)][hw][c]
__device__ __half g_planesH[(size_t)N_BATCH * 3 * HW * 32];

// ---- dynamic smem layout (bytes) ----
#define SM_W1S    0        // 2048 f32  [c][j]
#define SM_W2RS   8192     // 2048 f32  [j][32 rgb outputs]
#define SM_B1S    16384    // 64 f32
#define SM_W2SIG  16640    // 64 f32
#define SM_B2RS   16896    // 32 f32
#define SM_B2SIG  17024    // 1 f32 (+pad)
#define SM_TAPS   17152    // 4 warps x 32 x 12 int2 = 12288
#define SM_FEATS  29440    // 4 warps x 2 rays x 32*34 halves = 17408
#define SM_TOTAL  46848

// ---------- packed f32x2 helpers ----------
__device__ __forceinline__ u64 ffma2(u64 a, u64 b, u64 c) {
    u64 r; asm("fma.rn.f32x2 %0,%1,%2,%3;" : "=l"(r) : "l"(a), "l"(b), "l"(c)); return r;
}
__device__ __forceinline__ u64 pack2(float lo, float hi) {
    u64 r; asm("mov.b64 %0,{%1,%2};" : "=l"(r) : "f"(lo), "f"(hi)); return r;
}
__device__ __forceinline__ void unpack2(u64 d, float& lo, float& hi) {
    asm("mov.b64 {%0,%1},%2;" : "=f"(lo), "=f"(hi) : "l"(d));
}
__device__ __forceinline__ float softplus_f(float x) {
    return fmaxf(x, 0.f) + __logf(1.f + __expf(-fabsf(x)));
}

// ---------- kernel 0: [np][C][HW] f32 -> [np][HW][C] fp16 transpose ----------
__global__ void transpose_kernel(const float* __restrict__ in) {
    __shared__ float tile[32][33];
    int np  = blockIdx.y;
    int hw0 = blockIdx.x * 32;
    int tx = threadIdx.x, ty = threadIdx.y;
#pragma unroll
    for (int i = 0; i < 4; i++) {
        int cc = ty * 4 + i;
        tile[cc][tx] = in[(np * 32 + cc) * HW + hw0 + tx];
    }
    __syncthreads();
#pragma unroll
    for (int i = 0; i < 4; i++) {
        int row = ty * 4 + i;
        g_planesH[(size_t)(np * HW + hw0 + row) * 32 + tx] = __float2half(tile[tx][row]);
    }
}

// ---------- kernel 1: renderer, one warp per 2 rays, 4 blocks/SM ----------
__global__ __launch_bounds__(THREADS, 4) void render_kernel(
    const float* __restrict__ orig, const float* __restrict__ dirs,
    const float* __restrict__ w1, const float* __restrict__ b1,
    const float* __restrict__ w2, const float* __restrict__ b2,
    float* __restrict__ out)
{
    extern __shared__ __align__(16) unsigned char smem[];
    float* w1s    = (float*)(smem + SM_W1S);
    float* w2rs   = (float*)(smem + SM_W2RS);
    float* b1s    = (float*)(smem + SM_B1S);
    float* w2sigs = (float*)(smem + SM_W2SIG);
    float* b2rs   = (float*)(smem + SM_B2RS);
    float* b2sigp = (float*)(smem + SM_B2SIG);
    int2*  taps   = (int2*)(smem + SM_TAPS);
    u32*   featsb = (u32*)(smem + SM_FEATS);   // half2 lattice, pitch FPITCH u32

    const int tid = threadIdx.x;
    for (int i = tid; i < 2048; i += THREADS) w1s[i] = w1[i];
    if (tid < 64) b1s[tid] = b1[tid];
    for (int i = tid; i < 64 * 33; i += THREADS) {
        int j = i / 33, k = i - j * 33;
        float v = w2[i];
        if (k == 0) w2sigs[j] = v; else w2rs[j * 32 + (k - 1)] = v;
    }
    if (tid < 32) b2rs[tid] = b2[tid + 1];
    if (tid == 0) b2sigp[0] = b2[0];
    __syncthreads();

    const int w = tid >> 5, lane = tid & 31;
    const int rg0 = blockIdx.x * RPB + w * RPW;   // first ray of this warp
    const unsigned FULL = 0xffffffffu;

    const float t   = (lane + 0.5f) * 0.03125f;
    const float dep = 2.25f + 1.05f * t;

    // ---- stage 1+2 per ray: taps (lane = sample), then half2 gather ----
#pragma unroll
    for (int r = 0; r < RPW; r++) {
        const int rg = rg0 + r;
        const int n  = rg >> 14;
        const float ox = orig[rg * 3 + 0], oy = orig[rg * 3 + 1], oz = orig[rg * 3 + 2];
        const float dx = dirs[rg * 3 + 0], dy = dirs[rg * 3 + 1], dz = dirs[rg * 3 + 2];
        const float cx = 2.f * fmaf(dep, dx, ox);
        const float cy = 2.f * fmaf(dep, dy, oy);
        const float cz = 2.f * fmaf(dep, dz, oz);

#pragma unroll
        for (int p = 0; p < 3; p++) {
            float u = (p == 0) ? cx : (p == 1) ? cy : cx;
            float v = (p == 0) ? cy : (p == 1) ? cz : cz;
            float ix = ((u + 1.f) * 0.5f) * 255.f;
            float iy = ((v + 1.f) * 0.5f) * 255.f;
            float fx0 = floorf(ix), fy0 = floorf(iy);
            // fold the 1/3 plane-mean into the x-weights
            float a0 = (ix - fx0) * (1.f / 3.f);
            float a1 = ((fx0 + 1.f) - ix) * (1.f / 3.f);
            float bb0 = iy - fy0, bb1 = (fy0 + 1.f) - iy;
            int ix0 = (int)fminf(fmaxf(fx0, 0.f), 255.f);
            int ix1 = (int)fminf(fmaxf(fx0 + 1.f, 0.f), 255.f);
            int iy0 = (int)fminf(fmaxf(fy0, 0.f), 255.f);
            int iy1 = (int)fminf(fmaxf(fy0 + 1.f, 0.f), 255.f);
            int base = (n * 3 + p) * (HW * 32);
            int r0 = base + iy0 * (256 * 32);
            int r1 = base + iy1 * (256 * 32);
            int o = (w * 32 + lane) * 12 + p * 4;
            taps[o + 0] = make_int2(r0 + ix0 * 32, __float_as_int(a1 * bb1));
            taps[o + 1] = make_int2(r0 + ix1 * 32, __float_as_int(a0 * bb1));
            taps[o + 2] = make_int2(r1 + ix0 * 32, __float_as_int(a1 * bb0));
            taps[o + 3] = make_int2(r1 + ix1 * 32, __float_as_int(a0 * bb0));
        }
        __syncwarp();

        // gather: lanes = 4 channel-octets x 8 samples; each lane privately
        // accumulates its sample's 12 taps for 8 channels in half2 (HFMA2).
        {
            const int q    = lane & 3;            // channel octet
            const int sub  = lane >> 2;           // sample sub-index (0..7)
            const int cpos = q * 8;
            u32* feats = featsb + (w * 2 + r) * (32 * FPITCH);
#pragma unroll 2
            for (int sb = 0; sb < 32; sb += 8) {
                const int s = sb + sub;
                __half2 ac0 = __float2half2_rn(0.f);
                __half2 ac1 = ac0, ac2 = ac0, ac3 = ac0;
#pragma unroll
                for (int tp = 0; tp < 12; tp++) {
                    int2 tw = taps[(w * 32 + s) * 12 + tp];
                    __half2 wh = __float2half2_rn(__int_as_float(tw.y));
                    uint4 raw = *(const uint4*)&g_planesH[tw.x + cpos];
                    ac0 = __hfma2(wh, *reinterpret_cast<__half2*>(&raw.x), ac0);
                    ac1 = __hfma2(wh, *reinterpret_cast<__half2*>(&raw.y), ac1);
                    ac2 = __hfma2(wh, *reinterpret_cast<__half2*>(&raw.z), ac2);
                    ac3 = __hfma2(wh, *reinterpret_cast<__half2*>(&raw.w), ac3);
                }
                u32* f = feats + s * FPITCH + q * 4;
                f[0] = *reinterpret_cast<u32*>(&ac0);
                f[1] = *reinterpret_cast<u32*>(&ac1);
                f[2] = *reinterpret_cast<u32*>(&ac2);
                f[3] = *reinterpret_cast<u32*>(&ac3);
            }
        }
        __syncwarp();
    }

    // ---- MLP for both samples (lane's sample of ray0 and ray1) ----
    const u32* frow0 = featsb + (w * 2 + 0) * (32 * FPITCH) + lane * FPITCH;
    const u32* frow1 = featsb + (w * 2 + 1) * (32 * FPITCH) + lane * FPITCH;

    const float b2sig = b2sigp[0];
    float sig0 = b2sig, sig1 = b2sig;
    u64 a20[16], a21[16];
    const u64* b2d = (const u64*)b2rs;
#pragma unroll
    for (int k = 0; k < 16; k++) { a20[k] = b2d[k]; a21[k] = b2d[k]; }

    const ulonglong2* w1d2 = (const ulonglong2*)w1s;
    const ulonglong2* w2d2 = (const ulonglong2*)w2rs;
    const u64* b1d = (const u64*)b1s;

#pragma unroll
    for (int q = 0; q < 4; q++) {       // 16 hidden units per quarter
        u64 ac0[8], ac1[8];
#pragma unroll
        for (int jp = 0; jp < 8; jp++) { ac0[jp] = b1d[q * 8 + jp]; ac1[jp] = ac0[jp]; }

#pragma unroll 4
        for (int c2 = 0; c2 < 16; c2++) {      // channel pairs
            u32 r0b = frow0[c2], r1b = frow1[c2];
            float2 f0 = __half22float2(*reinterpret_cast<__half2*>(&r0b));
            float2 f1 = __half22float2(*reinterpret_cast<__half2*>(&r1b));
#pragma unroll
            for (int e = 0; e < 2; e++) {
                float fe0 = (e == 0) ? f0.x : f0.y;
                float fe1 = (e == 0) ? f1.x : f1.y;
                u64 f02 = pack2(fe0, fe0), f12 = pack2(fe1, fe1);
                const ulonglong2* wr = w1d2 + (2 * c2 + e) * 16 + q * 4;
#pragma unroll
                for (int jq = 0; jq < 4; jq++) {
                    ulonglong2 ww = wr[jq];
                    ac0[2 * jq]     = ffma2(f02, ww.x, ac0[2 * jq]);
                    ac0[2 * jq + 1] = ffma2(f02, ww.y, ac0[2 * jq + 1]);
                    ac1[2 * jq]     = ffma2(f12, ww.x, ac1[2 * jq]);
                    ac1[2 * jq + 1] = ffma2(f12, ww.y, ac1[2 * jq + 1]);
                }
            }
        }
        // consume the 16 hidden units of this quarter into layer 2
#pragma unroll 4
        for (int jp = 0; jp < 8; jp++) {
            int j0 = q * 16 + 2 * jp;
            float l0, h0, l1, h1;
            unpack2(ac0[jp], l0, h0);
            unpack2(ac1[jp], l1, h1);
            float h00 = softplus_f(l0), h01 = softplus_f(h0);
            float h10 = softplus_f(l1), h11 = softplus_f(h1);
            float ws0 = w2sigs[j0], ws1 = w2sigs[j0 + 1];
            sig0 = fmaf(h00, ws0, sig0); sig0 = fmaf(h01, ws1, sig0);
            sig1 = fmaf(h10, ws0, sig1); sig1 = fmaf(h11, ws1, sig1);
            u64 p00 = pack2(h00, h00), p01 = pack2(h01, h01);
            u64 p10 = pack2(h10, h10), p11 = pack2(h11, h11);
            const ulonglong2* wr0 = w2d2 + j0 * 8;
#pragma unroll
            for (int kq = 0; kq < 8; kq++) {
                ulonglong2 ww0 = wr0[kq];
                ulonglong2 ww1 = wr0[8 + kq];
                u64 v0 = ffma2(p00, ww0.x, a20[2 * kq]);
                u64 v1 = ffma2(p00, ww0.y, a20[2 * kq + 1]);
                a20[2 * kq]     = ffma2(p01, ww1.x, v0);
                a20[2 * kq + 1] = ffma2(p01, ww1.y, v1);
                u64 u0 = ffma2(p10, ww0.x, a21[2 * kq]);
                u64 u1 = ffma2(p10, ww0.y, a21[2 * kq + 1]);
                a21[2 * kq]     = ffma2(p11, ww1.x, u0);
                a21[2 * kq + 1] = ffma2(p11, ww1.y, u1);
            }
        }
    }

    // ---- ray marching per ray: warp scan over samples (lane = s) ----
#pragma unroll
    for (int r = 0; r < RPW; r++) {
        float sig = (r == 0) ? sig0 : sig1;
        float rgb[32];
#pragma unroll
        for (int k = 0; k < 16; k++) {
            u64 av = (r == 0) ? a20[k] : a21[k];
            float lo, hi; unpack2(av, lo, hi);
            rgb[2 * k]     = __fdividef(1.002f, 1.f + __expf(-lo)) - 0.001f;
            rgb[2 * k + 1] = __fdividef(1.002f, 1.f + __expf(-hi)) - 0.001f;
        }

        float sig_n = __shfl_down_sync(FULL, sig, 1);
        float dep_n = __shfl_down_sync(FULL, dep, 1);
        float alpha;
        if (lane < 31) {
            float delta = dep_n - dep;
            float dm = 0.5f * (sig + sig_n);
            float dens = softplus_f(dm - 1.f);
            alpha = 1.f - __expf(-delta * dens);
        } else {
            alpha = 0.f;
        }
        float gg = 1.f - alpha + 1e-10f;
        float pscan = gg;
#pragma unroll
        for (int off = 1; off < 32; off <<= 1) {
            float v = __shfl_up_sync(FULL, pscan, off);
            if (lane >= off) pscan *= v;
        }
        float T = __shfl_up_sync(FULL, pscan, 1);
        if (lane == 0) T = 1.f;
        float wgt = alpha * T;
        float wprev = __shfl_up_sync(FULL, wgt, 1);
        if (lane == 0) wprev = 0.f;
        float coeff = 0.5f * (wgt + wprev);

#pragma unroll
        for (int k = 0; k < 32; k++) rgb[k] *= coeff;
#pragma unroll
        for (int off = 16; off >= 1; off >>= 1) {
#pragma unroll
            for (int k = 0; k < 32; k++) rgb[k] += __shfl_xor_sync(FULL, rgb[k], off);
        }
        if (lane == 0) {
            float4* o4 = (float4*)(out + (rg0 + r) * 32);
#pragma unroll
            for (int k = 0; k < 8; k++)
                o4[k] = make_float4(rgb[4 * k], rgb[4 * k + 1], rgb[4 * k + 2], rgb[4 * k + 3]);
        }
    }
}

extern "C" void kernel_launch(void* const* d_in, const int* in_sizes, int n_in,
                              void* d_out, int out_size) {
    const float* vol  = (const float*)d_in[0];  // [2,3,32,256,256]
    const float* orig = (const float*)d_in[1];  // [2,16384,3]
    const float* dirs = (const float*)d_in[2];  // [2,16384,3]
    const float* w1   = (const float*)d_in[3];  // [32,64]
    const float* b1   = (const float*)d_in[4];  // [64]
    const float* w2   = (const float*)d_in[5];  // [64,33]
    const float* b2   = (const float*)d_in[6];  // [33]
    float* out = (float*)d_out;

    static int inited = 0;
    if (!inited) {
        cudaFuncSetAttribute(render_kernel,
                             cudaFuncAttributeMaxDynamicSharedMemorySize, SM_TOTAL);
        inited = 1;
    }

    dim3 tb(32, 8);
    dim3 tg(HW / 32, N_BATCH * 3);
    transpose_kernel<<<tg, tb>>>(vol);

    render_kernel<<<NRAYS / RPB, THREADS, SM_TOTAL>>>(orig, dirs, w1, b1, w2, b2, out);
}